// round 5
// baseline (speedup 1.0000x reference)
#include <cuda_runtime.h>

#define KNN      11
#define NPTS     50000
#define NSP      4000
#define NB       2
#define G        20
#define NCELL    (G*G*G)          // 8000
#define TMAIN    256
#define BLKS_MAIN ((NPTS + TMAIN - 1) / TMAIN)
#define CHUNK    ((NCELL + 255) / 256)   // 32

// ---------------- device scratch (no allocations allowed) ----------------
__device__ float          g_sx[NB][NSP], g_sy[NB][NSP], g_sz[NB][NSP]; // cell-sorted sites
__device__ unsigned short g_sidx[NB][NSP];                            // original site index
__device__ unsigned short g_cst[NB][NCELL + 1];                       // cell start offsets
__device__ float          g_box[NB][9];                               // mn[3], h[3], inv_h[3]
__device__ int            g_pcnt[NB][NCELL];
__device__ int            g_pcur[NB][NCELL];
__device__ float4         g_pts[NB][NPTS];                            // cell-sorted queries (w = orig idx)

__device__ __forceinline__ int cell_of(float x, float y, float z, const float* bx) {
    int cx = (int)((x - bx[0]) * bx[6]); cx = min(G - 1, max(0, cx));
    int cy = (int)((y - bx[1]) * bx[7]); cy = min(G - 1, max(0, cy));
    int cz = (int)((z - bx[2]) * bx[8]); cz = min(G - 1, max(0, cz));
    return (cx * G + cy) * G + cz;
}

// ---------------- kernel 1: bin sites into grid (one block per batch) ----------------
static constexpr int SM_SETUP = (NCELL + NCELL + 1 + 256) * 4 + 48 * 4;

__global__ void k_setup_sites(const float* __restrict__ spoints) {
    extern __shared__ int sm[];
    int*   cnt = sm;                 // NCELL
    int*   st  = cnt + NCELL;        // NCELL+1
    int*   tot = st + NCELL + 1;     // 256
    float* red = (float*)(tot + 256); // 48
    __shared__ float sbox[9];

    const int b = blockIdx.x, tid = threadIdx.x;
    const float* sp = spoints + (size_t)b * NSP * 3;

    for (int c = tid; c < NCELL; c += blockDim.x) g_pcnt[b][c] = 0;

    float mnx = 3e38f, mny = 3e38f, mnz = 3e38f;
    float mxx = -3e38f, mxy = -3e38f, mxz = -3e38f;
    for (int i = tid; i < NSP; i += blockDim.x) {
        float x = sp[3*i], y = sp[3*i+1], z = sp[3*i+2];
        mnx = fminf(mnx, x); mxx = fmaxf(mxx, x);
        mny = fminf(mny, y); mxy = fmaxf(mxy, y);
        mnz = fminf(mnz, z); mxz = fmaxf(mxz, z);
    }
#pragma unroll
    for (int o = 16; o; o >>= 1) {
        mnx = fminf(mnx, __shfl_xor_sync(0xffffffffu, mnx, o));
        mny = fminf(mny, __shfl_xor_sync(0xffffffffu, mny, o));
        mnz = fminf(mnz, __shfl_xor_sync(0xffffffffu, mnz, o));
        mxx = fmaxf(mxx, __shfl_xor_sync(0xffffffffu, mxx, o));
        mxy = fmaxf(mxy, __shfl_xor_sync(0xffffffffu, mxy, o));
        mxz = fmaxf(mxz, __shfl_xor_sync(0xffffffffu, mxz, o));
    }
    int w = tid >> 5;
    if ((tid & 31) == 0) {
        red[w] = mnx; red[8 + w] = mny; red[16 + w] = mnz;
        red[24 + w] = mxx; red[32 + w] = mxy; red[40 + w] = mxz;
    }
    __syncthreads();
    if (tid == 0) {
        float a0 = red[0], a1 = red[8], a2 = red[16], a3 = red[24], a4 = red[32], a5 = red[40];
        for (int i = 1; i < 8; i++) {
            a0 = fminf(a0, red[i]);      a1 = fminf(a1, red[8 + i]);  a2 = fminf(a2, red[16 + i]);
            a3 = fmaxf(a3, red[24 + i]); a4 = fmaxf(a4, red[32 + i]); a5 = fmaxf(a5, red[40 + i]);
        }
        float hx = (a3 - a0) * (1.0f / G) * 1.000001f + 1e-30f;
        float hy = (a4 - a1) * (1.0f / G) * 1.000001f + 1e-30f;
        float hz = (a5 - a2) * (1.0f / G) * 1.000001f + 1e-30f;
        sbox[0] = a0; sbox[1] = a1; sbox[2] = a2;
        sbox[3] = hx; sbox[4] = hy; sbox[5] = hz;
        sbox[6] = 1.0f / hx; sbox[7] = 1.0f / hy; sbox[8] = 1.0f / hz;
        for (int i = 0; i < 9; i++) g_box[b][i] = sbox[i];
    }
    __syncthreads();

    for (int c = tid; c < NCELL; c += blockDim.x) cnt[c] = 0;
    __syncthreads();
    for (int i = tid; i < NSP; i += blockDim.x) {
        int c = cell_of(sp[3*i], sp[3*i+1], sp[3*i+2], sbox);
        atomicAdd(&cnt[c], 1);
    }
    __syncthreads();

    int c0 = tid * CHUNK, s = 0;
    for (int j = 0; j < CHUNK; j++) { int c = c0 + j; if (c < NCELL) s += cnt[c]; }
    tot[tid] = s;
    __syncthreads();
    if (tid == 0) { int run = 0; for (int i = 0; i < 256; i++) { int v = tot[i]; tot[i] = run; run += v; } }
    __syncthreads();
    int run = tot[tid];
    for (int j = 0; j < CHUNK; j++) { int c = c0 + j; if (c < NCELL) { st[c] = run; run += cnt[c]; } }
    __syncthreads();
    if (tid == 0) st[NCELL] = NSP;
    __syncthreads();

    for (int c = tid; c <= NCELL; c += blockDim.x) g_cst[b][c] = (unsigned short)st[c];
    for (int c = tid; c < NCELL; c += blockDim.x) cnt[c] = st[c];   // cnt becomes cursor
    __syncthreads();

    for (int i = tid; i < NSP; i += blockDim.x) {
        float x = sp[3*i], y = sp[3*i+1], z = sp[3*i+2];
        int c = cell_of(x, y, z, sbox);
        int pos = atomicAdd(&cnt[c], 1);
        g_sx[b][pos] = x; g_sy[b][pos] = y; g_sz[b][pos] = z;
        g_sidx[b][pos] = (unsigned short)i;
    }
}

// ---------------- kernel 2: count queries per cell ----------------
__global__ void k_count_pts(const float* __restrict__ points) {
    const int b = blockIdx.y;
    const int p = blockIdx.x * blockDim.x + threadIdx.x;
    if (p >= NPTS) return;
    const float* pp = points + ((size_t)b * NPTS + p) * 3;
    float bx[9];
#pragma unroll
    for (int i = 0; i < 9; i++) bx[i] = g_box[b][i];
    atomicAdd(&g_pcnt[b][cell_of(pp[0], pp[1], pp[2], bx)], 1);
}

// ---------------- kernel 3: scan query counts -> cursors ----------------
__global__ void k_init_cursors() {
    const int b = blockIdx.x, tid = threadIdx.x;
    __shared__ int tot[256];
    int c0 = tid * CHUNK, s = 0;
    for (int j = 0; j < CHUNK; j++) { int c = c0 + j; if (c < NCELL) s += g_pcnt[b][c]; }
    tot[tid] = s;
    __syncthreads();
    if (tid == 0) { int run = 0; for (int i = 0; i < 256; i++) { int v = tot[i]; tot[i] = run; run += v; } }
    __syncthreads();
    int run = tot[tid];
    for (int j = 0; j < CHUNK; j++) { int c = c0 + j; if (c < NCELL) { g_pcur[b][c] = run; run += g_pcnt[b][c]; } }
}

// ---------------- kernel 4: scatter queries into cell-sorted order ----------------
__global__ void k_scatter_pts(const float* __restrict__ points) {
    const int b = blockIdx.y;
    const int p = blockIdx.x * blockDim.x + threadIdx.x;
    if (p >= NPTS) return;
    const float* pp = points + ((size_t)b * NPTS + p) * 3;
    float x = pp[0], y = pp[1], z = pp[2];
    float bx[9];
#pragma unroll
    for (int i = 0; i < 9; i++) bx[i] = g_box[b][i];
    int pos = atomicAdd(&g_pcur[b][cell_of(x, y, z, bx)], 1);
    g_pts[b][pos] = make_float4(x, y, z, __int_as_float(p));
}

// ---------------- kernel 5: main — WARP-UNIFORM expanding-box KNN + Voronoi ----------------
static constexpr int SM_MAIN = (3 * NSP + 9) * 4 + (NCELL + 1) * 2 + NSP * 2; // 72038

__global__ __launch_bounds__(TMAIN, 3) void k_main(float* __restrict__ out) {
    extern __shared__ float smf[];
    float* sx = smf;
    float* sy = sx + NSP;
    float* sz = sy + NSP;
    float* sbb = sz + NSP;                                 // 9 floats
    unsigned short* cst  = (unsigned short*)(sbb + 9);     // NCELL+1
    unsigned short* sidx = cst + (NCELL + 1);              // NSP

    const int b = blockIdx.y, tid = threadIdx.x;
    for (int i = tid; i < NSP; i += TMAIN) {
        sx[i] = g_sx[b][i]; sy[i] = g_sy[b][i]; sz[i] = g_sz[b][i];
        sidx[i] = g_sidx[b][i];
    }
    for (int i = tid; i <= NCELL; i += TMAIN) cst[i] = g_cst[b][i];
    if (tid < 9) sbb[tid] = g_box[b][tid];
    __syncthreads();

    // NO early return: keep full warps for reductions/ballots. Invalid lanes
    // compute a duplicate point and just don't write.
    int t = blockIdx.x * TMAIN + tid;
    const bool valid = (t < NPTS);
    if (!valid) t = NPTS - 1;

    const float4 P = g_pts[b][t];
    const float px = P.x, py = P.y, pz = P.z;
    const int orig = __float_as_int(P.w);

    const float mnx = sbb[0], mny = sbb[1], mnz = sbb[2];
    const float hx = sbb[3], hy = sbb[4], hz = sbb[5];
    const int cx = min(G - 1, max(0, (int)((px - mnx) * sbb[6])));
    const int cy = min(G - 1, max(0, (int)((py - mny) * sbb[7])));
    const int cz = min(G - 1, max(0, (int)((pz - mnz) * sbb[8])));

    float bd[KNN];
    int   bo[KNN];   // key = (orig_site_idx << 12) | sorted_pos  — lex order == jax tie-break
#pragma unroll
    for (int k = 0; k < KNN; k++) { bd[k] = 3.4e38f; bo[k] = 0x7FFFFFFF; }

    // Warp union of home cells -> one shared traversal for the whole warp.
    const unsigned FULL = 0xffffffffu;
    const int cxm = __reduce_min_sync(FULL, cx), cxM = __reduce_max_sync(FULL, cx);
    const int cym = __reduce_min_sync(FULL, cy), cyM = __reduce_max_sync(FULL, cy);
    const int czm = __reduce_min_sync(FULL, cz), czM = __reduce_max_sync(FULL, cz);

    int pxl = 1, pxh = 0, pyl = 1, pyh = 0, pzl = 1, pzh = 0;  // empty prev box
    bool ldone = false;

    for (int r = 0; ; r++) {
        const int xlo = max(cxm - r, 0), xhi = min(cxM + r, G - 1);
        const int ylo = max(cym - r, 0), yhi = min(cyM + r, G - 1);
        const int zlo = max(czm - r, 0), zhi = min(czM + r, G - 1);

        for (int X = xlo; X <= xhi; X++) {
            const bool xin = (X >= pxl) && (X <= pxh);
            for (int Y = ylo; Y <= yhi; Y++) {
                const bool yin = xin && (Y >= pyl) && (Y <= pyh);
                const int cbase = (X * G + Y) * G;
                for (int Z = zlo; Z <= zhi; Z++) {
                    if (yin && Z >= pzl && Z <= pzh) continue;   // already visited (uniform)
                    const int c = cbase + Z;
                    const int m0 = cst[c], m1 = cst[c + 1];      // uniform -> broadcast
                    if (!ldone) {
                        for (int m = m0; m < m1; m++) {          // uniform trip count
                            const float dx = px - sx[m];
                            const float dy = py - sy[m];
                            const float dz = pz - sz[m];
                            const float d2 = fmaf(dz, dz, fmaf(dy, dy, dx * dx));
                            if (d2 <= bd[KNN - 1]) {
                                float d = d2;
                                int kk = ((int)sidx[m] << 12) | m;
#pragma unroll
                                for (int k = 0; k < KNN; k++) {
                                    const bool sw = (d < bd[k]) || ((d == bd[k]) && (kk < bo[k]));
                                    if (sw) {
                                        const float td = bd[k]; bd[k] = d;  d = td;
                                        const int   ti = bo[k]; bo[k] = kk; kk = ti;
                                    }
                                }
                            }
                        }
                    }
                }
            }
        }

        const bool full = (xlo == 0 && xhi == G - 1 && ylo == 0 && yhi == G - 1 &&
                           zlo == 0 && zhi == G - 1);
        if (!ldone) {
            // Per-lane ring bound against the WARP's visited box. Clamped faces need
            // no bound (all sites live inside the grid bbox).
            float bnd = 3.0e38f;
            if (xlo > 0)     bnd = fminf(bnd, px - (mnx + (float)xlo * hx));
            if (xhi < G - 1) bnd = fminf(bnd, (mnx + (float)(xhi + 1) * hx) - px);
            if (ylo > 0)     bnd = fminf(bnd, py - (mny + (float)ylo * hy));
            if (yhi < G - 1) bnd = fminf(bnd, (mny + (float)(yhi + 1) * hy) - py);
            if (zlo > 0)     bnd = fminf(bnd, pz - (mnz + (float)zlo * hz));
            if (zhi < G - 1) bnd = fminf(bnd, (mnz + (float)(zhi + 1) * hz) - pz);
            ldone = full || (bd[KNN - 1] < 3.0e38f && bnd > 0.0f &&
                             bnd * bnd >= bd[KNN - 1] * 1.0002f);
        }
        if (__all_sync(FULL, ldone) || full) break;
        pxl = xlo; pxh = xhi; pyl = ylo; pyh = yhi; pzl = zlo; pzh = zhi;
    }

    // Voronoi-edge epilogue on the 11 selected sites (slots 1..10 order irrelevant: min)
    const int p0 = bo[0] & 4095;
    const float cx0 = sx[p0], cy0 = sy[p0], cz0 = sz[p0];
    const float tx = px - cx0, ty = py - cy0, tz = pz - cz0;
    float best = 3.4e38f;
#pragma unroll
    for (int j = 1; j < KNN; j++) {
        const int pj = bo[j] & 4095;
        const float ex = sx[pj] - cx0, ey = sy[pj] - cy0, ez = sz[pj] - cz0;
        const float el2 = fmaf(ez, ez, fmaf(ey, ey, ex * ex));
        const float dp  = fmaf(tz, ez, fmaf(ty, ey, tx * ex));
        const float tt  = fmaf(-0.5f, el2, dp) * rsqrtf(el2);  // (dp - el2/2)/sqrt(el2)
        best = fminf(best, tt * tt);
    }
    if (valid) out[(size_t)b * NPTS + orig] = best;
}

// ---------------- launch ----------------
extern "C" void kernel_launch(void* const* d_in, const int* in_sizes, int n_in,
                              void* d_out, int out_size)
{
    const float* points  = (const float*)d_in[0];
    const float* spoints = (const float*)d_in[1];
    float* out = (float*)d_out;

    cudaFuncSetAttribute(k_setup_sites, cudaFuncAttributeMaxDynamicSharedMemorySize, SM_SETUP);
    cudaFuncSetAttribute(k_main,        cudaFuncAttributeMaxDynamicSharedMemorySize, SM_MAIN);

    k_setup_sites<<<NB, 256, SM_SETUP>>>(spoints);
    dim3 gp((NPTS + 255) / 256, NB);
    k_count_pts<<<gp, 256>>>(points);
    k_init_cursors<<<NB, 256>>>();
    k_scatter_pts<<<gp, 256>>>(points);
    k_main<<<dim3(BLKS_MAIN, NB), TMAIN, SM_MAIN>>>(out);
}

// round 6
// speedup vs baseline: 2.0106x; 2.0106x over previous
#include <cuda_runtime.h>

#define KNN      11
#define NPTS     50000
#define NSP      4000
#define NB       2
#define G        20
#define NCELL    (G*G*G)                  // 8000
#define CHUNK    ((NCELL + 255) / 256)    // 32
#define MAXT     (NPTS / 32 + NCELL)      // 9563 worst-case tasks per batch
#define WPB      8                        // warps per main block
#define TMAIN    (WPB * 32)
#define GRID_MAIN ((MAXT + WPB - 1) / WPB)

// ---------------- device scratch (no allocations allowed) ----------------
__device__ float4         g_spk[NB][NSP];       // cell-sorted sites, w = int_as_float(sidx<<12)
__device__ unsigned short g_cst[NB][NCELL + 1]; // site cell start offsets
__device__ float          g_box[NB][9];         // mn[3], h[3], inv_h[3]
__device__ int            g_pcnt[NB][NCELL];
__device__ int            g_pcur[NB][NCELL];
__device__ float4         g_pts[NB][NPTS];      // cell-sorted queries (w = orig idx)
__device__ int2           g_tasks[NB][MAXT];    // x = cell | (nvalid<<16), y = qstart
__device__ int            g_ntasks[NB];

__device__ __forceinline__ int cell_of(float x, float y, float z, const float* bx) {
    int cx = (int)((x - bx[0]) * bx[6]); cx = min(G - 1, max(0, cx));
    int cy = (int)((y - bx[1]) * bx[7]); cy = min(G - 1, max(0, cy));
    int cz = (int)((z - bx[2]) * bx[8]); cz = min(G - 1, max(0, cz));
    return (cx * G + cy) * G + cz;
}

// ---------------- kernel 1: bin sites into grid (one block per batch) ----------------
static constexpr int SM_SETUP = (NCELL + NCELL + 1 + 256) * 4 + 48 * 4;

__global__ void k_setup_sites(const float* __restrict__ spoints) {
    extern __shared__ int sm[];
    int*   cnt = sm;                  // NCELL
    int*   st  = cnt + NCELL;         // NCELL+1
    int*   tot = st + NCELL + 1;      // 256
    float* red = (float*)(tot + 256); // 48
    __shared__ float sbox[9];

    const int b = blockIdx.x, tid = threadIdx.x;
    const float* sp = spoints + (size_t)b * NSP * 3;

    if (tid == 0) g_ntasks[b] = 0;
    for (int c = tid; c < NCELL; c += blockDim.x) g_pcnt[b][c] = 0;

    float mnx = 3e38f, mny = 3e38f, mnz = 3e38f;
    float mxx = -3e38f, mxy = -3e38f, mxz = -3e38f;
    for (int i = tid; i < NSP; i += blockDim.x) {
        float x = sp[3*i], y = sp[3*i+1], z = sp[3*i+2];
        mnx = fminf(mnx, x); mxx = fmaxf(mxx, x);
        mny = fminf(mny, y); mxy = fmaxf(mxy, y);
        mnz = fminf(mnz, z); mxz = fmaxf(mxz, z);
    }
#pragma unroll
    for (int o = 16; o; o >>= 1) {
        mnx = fminf(mnx, __shfl_xor_sync(0xffffffffu, mnx, o));
        mny = fminf(mny, __shfl_xor_sync(0xffffffffu, mny, o));
        mnz = fminf(mnz, __shfl_xor_sync(0xffffffffu, mnz, o));
        mxx = fmaxf(mxx, __shfl_xor_sync(0xffffffffu, mxx, o));
        mxy = fmaxf(mxy, __shfl_xor_sync(0xffffffffu, mxy, o));
        mxz = fmaxf(mxz, __shfl_xor_sync(0xffffffffu, mxz, o));
    }
    int w = tid >> 5;
    if ((tid & 31) == 0) {
        red[w] = mnx; red[8 + w] = mny; red[16 + w] = mnz;
        red[24 + w] = mxx; red[32 + w] = mxy; red[40 + w] = mxz;
    }
    __syncthreads();
    if (tid == 0) {
        float a0 = red[0], a1 = red[8], a2 = red[16], a3 = red[24], a4 = red[32], a5 = red[40];
        for (int i = 1; i < 8; i++) {
            a0 = fminf(a0, red[i]);      a1 = fminf(a1, red[8 + i]);  a2 = fminf(a2, red[16 + i]);
            a3 = fmaxf(a3, red[24 + i]); a4 = fmaxf(a4, red[32 + i]); a5 = fmaxf(a5, red[40 + i]);
        }
        float hx = (a3 - a0) * (1.0f / G) * 1.000001f + 1e-30f;
        float hy = (a4 - a1) * (1.0f / G) * 1.000001f + 1e-30f;
        float hz = (a5 - a2) * (1.0f / G) * 1.000001f + 1e-30f;
        sbox[0] = a0; sbox[1] = a1; sbox[2] = a2;
        sbox[3] = hx; sbox[4] = hy; sbox[5] = hz;
        sbox[6] = 1.0f / hx; sbox[7] = 1.0f / hy; sbox[8] = 1.0f / hz;
        for (int i = 0; i < 9; i++) g_box[b][i] = sbox[i];
    }
    __syncthreads();

    for (int c = tid; c < NCELL; c += blockDim.x) cnt[c] = 0;
    __syncthreads();
    for (int i = tid; i < NSP; i += blockDim.x) {
        int c = cell_of(sp[3*i], sp[3*i+1], sp[3*i+2], sbox);
        atomicAdd(&cnt[c], 1);
    }
    __syncthreads();

    int c0 = tid * CHUNK, s = 0;
    for (int j = 0; j < CHUNK; j++) { int c = c0 + j; if (c < NCELL) s += cnt[c]; }
    tot[tid] = s;
    __syncthreads();
    if (tid == 0) { int run = 0; for (int i = 0; i < 256; i++) { int v = tot[i]; tot[i] = run; run += v; } }
    __syncthreads();
    int run = tot[tid];
    for (int j = 0; j < CHUNK; j++) { int c = c0 + j; if (c < NCELL) { st[c] = run; run += cnt[c]; } }
    __syncthreads();
    if (tid == 0) st[NCELL] = NSP;
    __syncthreads();

    for (int c = tid; c <= NCELL; c += blockDim.x) g_cst[b][c] = (unsigned short)st[c];
    for (int c = tid; c < NCELL; c += blockDim.x) cnt[c] = st[c];   // cnt becomes cursor
    __syncthreads();

    for (int i = tid; i < NSP; i += blockDim.x) {
        float x = sp[3*i], y = sp[3*i+1], z = sp[3*i+2];
        int c = cell_of(x, y, z, sbox);
        int pos = atomicAdd(&cnt[c], 1);
        g_spk[b][pos] = make_float4(x, y, z, __int_as_float(i << 12));
    }
}

// ---------------- kernel 2: count queries per cell ----------------
__global__ void k_count_pts(const float* __restrict__ points) {
    const int b = blockIdx.y;
    const int p = blockIdx.x * blockDim.x + threadIdx.x;
    if (p >= NPTS) return;
    const float* pp = points + ((size_t)b * NPTS + p) * 3;
    float bx[9];
#pragma unroll
    for (int i = 0; i < 9; i++) bx[i] = g_box[b][i];
    atomicAdd(&g_pcnt[b][cell_of(pp[0], pp[1], pp[2], bx)], 1);
}

// ---------------- kernel 3: scan query counts -> cursors + build task queue ----------------
__global__ void k_init_cursors() {
    const int b = blockIdx.x, tid = threadIdx.x;
    __shared__ int tot[256];
    int c0 = tid * CHUNK, s = 0;
    for (int j = 0; j < CHUNK; j++) { int c = c0 + j; if (c < NCELL) s += g_pcnt[b][c]; }
    tot[tid] = s;
    __syncthreads();
    if (tid == 0) { int run = 0; for (int i = 0; i < 256; i++) { int v = tot[i]; tot[i] = run; run += v; } }
    __syncthreads();
    int run = tot[tid];
    for (int j = 0; j < CHUNK; j++) {
        int c = c0 + j;
        if (c < NCELL) {
            int cnt = g_pcnt[b][c];
            g_pcur[b][c] = run;
            // emit one task per 32 queries of this cell
            int qs = run, rem = cnt;
            while (rem > 0) {
                int nv = min(rem, 32);
                int pos = atomicAdd(&g_ntasks[b], 1);
                g_tasks[b][pos] = make_int2(c | (nv << 16), qs);
                qs += nv; rem -= nv;
            }
            run += cnt;
        }
    }
}

// ---------------- kernel 4: scatter queries into cell-sorted order ----------------
__global__ void k_scatter_pts(const float* __restrict__ points) {
    const int b = blockIdx.y;
    const int p = blockIdx.x * blockDim.x + threadIdx.x;
    if (p >= NPTS) return;
    const float* pp = points + ((size_t)b * NPTS + p) * 3;
    float x = pp[0], y = pp[1], z = pp[2];
    float bx[9];
#pragma unroll
    for (int i = 0; i < 9; i++) bx[i] = g_box[b][i];
    int pos = atomicAdd(&g_pcur[b][cell_of(x, y, z, bx)], 1);
    g_pts[b][pos] = make_float4(x, y, z, __int_as_float(p));
}

// ---------------- kernel 5: main — per-warp single-cell task, uniform expanding box ----------------
static constexpr int SM_MAIN = NSP * 16 + 16 * 4 + (NCELL + 1) * 2;  // 64000 + 64 + 16002 = 80066

__global__ __launch_bounds__(TMAIN, 2) void k_main(float* __restrict__ out) {
    extern __shared__ float smf[];
    float4* spk = (float4*)smf;                        // NSP float4
    float*  sbb = (float*)(spk + NSP);                 // 9 floats (+pad)
    unsigned short* cst = (unsigned short*)(sbb + 16); // NCELL+1

    const int b = blockIdx.y, tid = threadIdx.x;
    const int ntasks = g_ntasks[b];
    const int tbase = blockIdx.x * WPB;
    if (tbase >= ntasks) return;                       // whole block idle: skip SMEM fill

    for (int i = tid; i < NSP; i += TMAIN) spk[i] = g_spk[b][i];
    for (int i = tid; i <= NCELL; i += TMAIN) cst[i] = g_cst[b][i];
    if (tid < 9) sbb[tid] = g_box[b][tid];
    __syncthreads();

    const int wid = tid >> 5, lane = tid & 31;
    const int tsk = tbase + wid;
    if (tsk >= ntasks) return;

    const int2 T = g_tasks[b][tsk];                    // uniform across warp
    const int cell = T.x & 0xffff;
    const int nv   = T.x >> 16;
    const int cx = cell / (G * G), cy = (cell / G) % G, cz = cell % G;

    const bool valid = (lane < nv);
    const int q = T.y + (valid ? lane : nv - 1);

    const float4 P = g_pts[b][q];
    const float px = P.x, py = P.y, pz = P.z;
    const int orig = __float_as_int(P.w);

    const float mnx = sbb[0], mny = sbb[1], mnz = sbb[2];
    const float hx = sbb[3], hy = sbb[4], hz = sbb[5];

    float bd[KNN];
    int   bo[KNN];   // key = (orig_site_idx << 12) | sorted_pos — lex order == jax tie-break
#pragma unroll
    for (int k = 0; k < KNN; k++) { bd[k] = 3.4e38f; bo[k] = 0x7FFFFFFF; }

    const unsigned FULL = 0xffffffffu;
    int pxl = 1, pxh = 0, pyl = 1, pyh = 0, pzl = 1, pzh = 0;  // empty prev box
    bool ldone = false;

    for (int r = 0; ; r++) {
        const int xlo = max(cx - r, 0), xhi = min(cx + r, G - 1);
        const int ylo = max(cy - r, 0), yhi = min(cy + r, G - 1);
        const int zlo = max(cz - r, 0), zhi = min(cz + r, G - 1);

        for (int X = xlo; X <= xhi; X++) {
            const bool xin = (X >= pxl) && (X <= pxh);
            for (int Y = ylo; Y <= yhi; Y++) {
                const bool yin = xin && (Y >= pyl) && (Y <= pyh);
                const int cbase = (X * G + Y) * G;
                for (int Z = zlo; Z <= zhi; Z++) {
                    if (yin && Z >= pzl && Z <= pzh) continue;   // visited (uniform)
                    const int c = cbase + Z;
                    const int m0 = cst[c], m1 = cst[c + 1];      // uniform -> broadcast
                    for (int m = m0; m < m1; m++) {
                        const float4 S = spk[m];                 // LDS.128 broadcast
                        const float dx = px - S.x;
                        const float dy = py - S.y;
                        const float dz = pz - S.z;
                        const float d2 = fmaf(dz, dz, fmaf(dy, dy, dx * dx));
                        if (d2 <= bd[KNN - 1]) {
                            float d = d2;
                            int kk = __float_as_int(S.w) | m;
#pragma unroll
                            for (int k = 0; k < KNN; k++) {
                                const bool sw = (d < bd[k]) || ((d == bd[k]) && (kk < bo[k]));
                                if (sw) {
                                    const float td = bd[k]; bd[k] = d;  d = td;
                                    const int   ti = bo[k]; bo[k] = kk; kk = ti;
                                }
                            }
                        }
                    }
                }
            }
        }

        const bool full = (xlo == 0 && xhi == G - 1 && ylo == 0 && yhi == G - 1 &&
                           zlo == 0 && zhi == G - 1);
        if (!ldone) {
            // Per-lane ring bound against the visited box; clamped faces need no bound.
            float bnd = 3.0e38f;
            if (xlo > 0)     bnd = fminf(bnd, px - (mnx + (float)xlo * hx));
            if (xhi < G - 1) bnd = fminf(bnd, (mnx + (float)(xhi + 1) * hx) - px);
            if (ylo > 0)     bnd = fminf(bnd, py - (mny + (float)ylo * hy));
            if (yhi < G - 1) bnd = fminf(bnd, (mny + (float)(yhi + 1) * hy) - py);
            if (zlo > 0)     bnd = fminf(bnd, pz - (mnz + (float)zlo * hz));
            if (zhi < G - 1) bnd = fminf(bnd, (mnz + (float)(zhi + 1) * hz) - pz);
            ldone = full || (bd[KNN - 1] < 3.0e38f && bnd > 0.0f &&
                             bnd * bnd >= bd[KNN - 1] * 1.0002f);
        }
        if (__all_sync(FULL, ldone) || full) break;
        pxl = xlo; pxh = xhi; pyl = ylo; pyh = yhi; pzl = zlo; pzh = zhi;
    }

    // Voronoi-edge epilogue on the 11 selected sites (slots 1..10 order irrelevant: min)
    const int p0 = bo[0] & 4095;
    const float4 C = spk[p0];
    const float tx = px - C.x, ty = py - C.y, tz = pz - C.z;
    float best = 3.4e38f;
#pragma unroll
    for (int j = 1; j < KNN; j++) {
        const int pj = bo[j] & 4095;
        const float4 E = spk[pj];
        const float ex = E.x - C.x, ey = E.y - C.y, ez = E.z - C.z;
        const float el2 = fmaf(ez, ez, fmaf(ey, ey, ex * ex));
        const float dp  = fmaf(tz, ez, fmaf(ty, ey, tx * ex));
        const float tt  = fmaf(-0.5f, el2, dp) * rsqrtf(el2);  // (dp - el2/2)/sqrt(el2)
        best = fminf(best, tt * tt);
    }
    if (valid) out[(size_t)b * NPTS + orig] = best;
}

// ---------------- launch ----------------
extern "C" void kernel_launch(void* const* d_in, const int* in_sizes, int n_in,
                              void* d_out, int out_size)
{
    const float* points  = (const float*)d_in[0];
    const float* spoints = (const float*)d_in[1];
    float* out = (float*)d_out;

    cudaFuncSetAttribute(k_setup_sites, cudaFuncAttributeMaxDynamicSharedMemorySize, SM_SETUP);
    cudaFuncSetAttribute(k_main,        cudaFuncAttributeMaxDynamicSharedMemorySize, SM_MAIN);

    k_setup_sites<<<NB, 256, SM_SETUP>>>(spoints);
    dim3 gp((NPTS + 255) / 256, NB);
    k_count_pts<<<gp, 256>>>(points);
    k_init_cursors<<<NB, 256>>>();
    k_scatter_pts<<<gp, 256>>>(points);
    k_main<<<dim3(GRID_MAIN, NB), TMAIN, SM_MAIN>>>(out);
}

// round 7
// speedup vs baseline: 2.0123x; 1.0008x over previous
#include <cuda_runtime.h>

#define KNN      11
#define NPTS     50000
#define NSP      4000
#define NB       2
#define G        20
#define NCELL    (G*G*G)                  // 8000
#define CHUNK    ((NCELL + 255) / 256)    // 32
#define MAXT     (NPTS / 32 + NCELL)      // 9563 worst-case tasks per batch
#define WPB      8                        // warps per main block
#define TMAIN    (WPB * 32)
#define GRID_MAIN ((MAXT + WPB - 1) / WPB)

// ---------------- device scratch (no allocations allowed) ----------------
__device__ float4         g_spk[NB][NSP];       // cell-sorted sites, w = int_as_float(sidx<<12)
__device__ unsigned short g_cst[NB][NCELL + 1]; // site cell start offsets
__device__ float          g_box[NB][9];         // mn[3], h[3], inv_h[3]
__device__ int            g_pcnt[NB][NCELL];
__device__ int            g_pcur[NB][NCELL];
__device__ float4         g_pts[NB][NPTS];      // cell-sorted queries (w = orig idx)
__device__ int2           g_tasks[NB][MAXT];    // x = cell | (nvalid<<16), y = qstart
__device__ int            g_ntasks[NB];

__device__ __forceinline__ int cell_of(float x, float y, float z, const float* bx) {
    int cx = (int)((x - bx[0]) * bx[6]); cx = min(G - 1, max(0, cx));
    int cy = (int)((y - bx[1]) * bx[7]); cy = min(G - 1, max(0, cy));
    int cz = (int)((z - bx[2]) * bx[8]); cz = min(G - 1, max(0, cz));
    return (cx * G + cy) * G + cz;
}

// ---------------- kernel 1: bin sites into grid (one block per batch) ----------------
static constexpr int SM_SETUP = (NCELL + NCELL + 1 + 256) * 4 + 48 * 4;

__global__ void k_setup_sites(const float* __restrict__ spoints) {
    extern __shared__ int sm[];
    int*   cnt = sm;                  // NCELL
    int*   st  = cnt + NCELL;         // NCELL+1
    int*   tot = st + NCELL + 1;      // 256
    float* red = (float*)(tot + 256); // 48
    __shared__ float sbox[9];

    const int b = blockIdx.x, tid = threadIdx.x;
    const float* sp = spoints + (size_t)b * NSP * 3;

    if (tid == 0) g_ntasks[b] = 0;
    for (int c = tid; c < NCELL; c += blockDim.x) g_pcnt[b][c] = 0;

    float mnx = 3e38f, mny = 3e38f, mnz = 3e38f;
    float mxx = -3e38f, mxy = -3e38f, mxz = -3e38f;
    for (int i = tid; i < NSP; i += blockDim.x) {
        float x = sp[3*i], y = sp[3*i+1], z = sp[3*i+2];
        mnx = fminf(mnx, x); mxx = fmaxf(mxx, x);
        mny = fminf(mny, y); mxy = fmaxf(mxy, y);
        mnz = fminf(mnz, z); mxz = fmaxf(mxz, z);
    }
#pragma unroll
    for (int o = 16; o; o >>= 1) {
        mnx = fminf(mnx, __shfl_xor_sync(0xffffffffu, mnx, o));
        mny = fminf(mny, __shfl_xor_sync(0xffffffffu, mny, o));
        mnz = fminf(mnz, __shfl_xor_sync(0xffffffffu, mnz, o));
        mxx = fmaxf(mxx, __shfl_xor_sync(0xffffffffu, mxx, o));
        mxy = fmaxf(mxy, __shfl_xor_sync(0xffffffffu, mxy, o));
        mxz = fmaxf(mxz, __shfl_xor_sync(0xffffffffu, mxz, o));
    }
    int w = tid >> 5;
    if ((tid & 31) == 0) {
        red[w] = mnx; red[8 + w] = mny; red[16 + w] = mnz;
        red[24 + w] = mxx; red[32 + w] = mxy; red[40 + w] = mxz;
    }
    __syncthreads();
    if (tid == 0) {
        float a0 = red[0], a1 = red[8], a2 = red[16], a3 = red[24], a4 = red[32], a5 = red[40];
        for (int i = 1; i < 8; i++) {
            a0 = fminf(a0, red[i]);      a1 = fminf(a1, red[8 + i]);  a2 = fminf(a2, red[16 + i]);
            a3 = fmaxf(a3, red[24 + i]); a4 = fmaxf(a4, red[32 + i]); a5 = fmaxf(a5, red[40 + i]);
        }
        float hx = (a3 - a0) * (1.0f / G) * 1.000001f + 1e-30f;
        float hy = (a4 - a1) * (1.0f / G) * 1.000001f + 1e-30f;
        float hz = (a5 - a2) * (1.0f / G) * 1.000001f + 1e-30f;
        sbox[0] = a0; sbox[1] = a1; sbox[2] = a2;
        sbox[3] = hx; sbox[4] = hy; sbox[5] = hz;
        sbox[6] = 1.0f / hx; sbox[7] = 1.0f / hy; sbox[8] = 1.0f / hz;
        for (int i = 0; i < 9; i++) g_box[b][i] = sbox[i];
    }
    __syncthreads();

    for (int c = tid; c < NCELL; c += blockDim.x) cnt[c] = 0;
    __syncthreads();
    for (int i = tid; i < NSP; i += blockDim.x) {
        int c = cell_of(sp[3*i], sp[3*i+1], sp[3*i+2], sbox);
        atomicAdd(&cnt[c], 1);
    }
    __syncthreads();

    int c0 = tid * CHUNK, s = 0;
    for (int j = 0; j < CHUNK; j++) { int c = c0 + j; if (c < NCELL) s += cnt[c]; }
    tot[tid] = s;
    __syncthreads();
    if (tid == 0) { int run = 0; for (int i = 0; i < 256; i++) { int v = tot[i]; tot[i] = run; run += v; } }
    __syncthreads();
    int run = tot[tid];
    for (int j = 0; j < CHUNK; j++) { int c = c0 + j; if (c < NCELL) { st[c] = run; run += cnt[c]; } }
    __syncthreads();
    if (tid == 0) st[NCELL] = NSP;
    __syncthreads();

    for (int c = tid; c <= NCELL; c += blockDim.x) g_cst[b][c] = (unsigned short)st[c];
    for (int c = tid; c < NCELL; c += blockDim.x) cnt[c] = st[c];   // cnt becomes cursor
    __syncthreads();

    for (int i = tid; i < NSP; i += blockDim.x) {
        float x = sp[3*i], y = sp[3*i+1], z = sp[3*i+2];
        int c = cell_of(x, y, z, sbox);
        int pos = atomicAdd(&cnt[c], 1);
        g_spk[b][pos] = make_float4(x, y, z, __int_as_float(i << 12));
    }
}

// ---------------- kernel 2: count queries per cell ----------------
__global__ void k_count_pts(const float* __restrict__ points) {
    const int b = blockIdx.y;
    const int p = blockIdx.x * blockDim.x + threadIdx.x;
    if (p >= NPTS) return;
    const float* pp = points + ((size_t)b * NPTS + p) * 3;
    float bx[9];
#pragma unroll
    for (int i = 0; i < 9; i++) bx[i] = g_box[b][i];
    atomicAdd(&g_pcnt[b][cell_of(pp[0], pp[1], pp[2], bx)], 1);
}

// ---------------- kernel 3: scan query counts -> cursors + build task queue ----------------
__global__ void k_init_cursors() {
    const int b = blockIdx.x, tid = threadIdx.x;
    __shared__ int tot[256];
    int c0 = tid * CHUNK, s = 0;
    for (int j = 0; j < CHUNK; j++) { int c = c0 + j; if (c < NCELL) s += g_pcnt[b][c]; }
    tot[tid] = s;
    __syncthreads();
    if (tid == 0) { int run = 0; for (int i = 0; i < 256; i++) { int v = tot[i]; tot[i] = run; run += v; } }
    __syncthreads();
    int run = tot[tid];
    for (int j = 0; j < CHUNK; j++) {
        int c = c0 + j;
        if (c < NCELL) {
            int cnt = g_pcnt[b][c];
            g_pcur[b][c] = run;
            // emit one task per 32 queries of this cell
            int qs = run, rem = cnt;
            while (rem > 0) {
                int nv = min(rem, 32);
                int pos = atomicAdd(&g_ntasks[b], 1);
                g_tasks[b][pos] = make_int2(c | (nv << 16), qs);
                qs += nv; rem -= nv;
            }
            run += cnt;
        }
    }
}

// ---------------- kernel 4: scatter queries into cell-sorted order ----------------
__global__ void k_scatter_pts(const float* __restrict__ points) {
    const int b = blockIdx.y;
    const int p = blockIdx.x * blockDim.x + threadIdx.x;
    if (p >= NPTS) return;
    const float* pp = points + ((size_t)b * NPTS + p) * 3;
    float x = pp[0], y = pp[1], z = pp[2];
    float bx[9];
#pragma unroll
    for (int i = 0; i < 9; i++) bx[i] = g_box[b][i];
    int pos = atomicAdd(&g_pcur[b][cell_of(x, y, z, bx)], 1);
    g_pts[b][pos] = make_float4(x, y, z, __int_as_float(p));
}

// ---------------- kernel 5: main — per-warp single-cell task, uniform expanding box ----------------
static constexpr int SM_MAIN = NSP * 16 + 16 * 4 + (NCELL + 1) * 2;  // 64000 + 64 + 16002 = 80066

__global__ __launch_bounds__(TMAIN, 2) void k_main(float* __restrict__ out) {
    extern __shared__ float smf[];
    float4* spk = (float4*)smf;                        // NSP float4
    float*  sbb = (float*)(spk + NSP);                 // 9 floats (+pad)
    unsigned short* cst = (unsigned short*)(sbb + 16); // NCELL+1

    const int b = blockIdx.y, tid = threadIdx.x;
    const int ntasks = g_ntasks[b];
    const int tbase = blockIdx.x * WPB;
    if (tbase >= ntasks) return;                       // whole block idle: skip SMEM fill

    for (int i = tid; i < NSP; i += TMAIN) spk[i] = g_spk[b][i];
    for (int i = tid; i <= NCELL; i += TMAIN) cst[i] = g_cst[b][i];
    if (tid < 9) sbb[tid] = g_box[b][tid];
    __syncthreads();

    const int wid = tid >> 5, lane = tid & 31;
    const int tsk = tbase + wid;
    if (tsk >= ntasks) return;

    const int2 T = g_tasks[b][tsk];                    // uniform across warp
    const int cell = T.x & 0xffff;
    const int nv   = T.x >> 16;
    const int cx = cell / (G * G), cy = (cell / G) % G, cz = cell % G;

    const bool valid = (lane < nv);
    const int q = T.y + (valid ? lane : nv - 1);

    const float4 P = g_pts[b][q];
    const float px = P.x, py = P.y, pz = P.z;
    const int orig = __float_as_int(P.w);

    const float mnx = sbb[0], mny = sbb[1], mnz = sbb[2];
    const float hx = sbb[3], hy = sbb[4], hz = sbb[5];

    float bd[KNN];
    int   bo[KNN];   // key = (orig_site_idx << 12) | sorted_pos — lex order == jax tie-break
#pragma unroll
    for (int k = 0; k < KNN; k++) { bd[k] = 3.4e38f; bo[k] = 0x7FFFFFFF; }

    const unsigned FULL = 0xffffffffu;
    int pxl = 1, pxh = 0, pyl = 1, pyh = 0, pzl = 1, pzh = 0;  // empty prev box
    bool ldone = false;

    for (int r = 0; ; r++) {
        const int xlo = max(cx - r, 0), xhi = min(cx + r, G - 1);
        const int ylo = max(cy - r, 0), yhi = min(cy + r, G - 1);
        const int zlo = max(cz - r, 0), zhi = min(cz + r, G - 1);

        for (int X = xlo; X <= xhi; X++) {
            const bool xin = (X >= pxl) && (X <= pxh);
            for (int Y = ylo; Y <= yhi; Y++) {
                const bool yin = xin && (Y >= pyl) && (Y <= pyh);
                const int cbase = (X * G + Y) * G;
                for (int Z = zlo; Z <= zhi; Z++) {
                    if (yin && Z >= pzl && Z <= pzh) continue;   // visited (uniform)
                    const int c = cbase + Z;
                    const int m0 = cst[c], m1 = cst[c + 1];      // uniform -> broadcast
                    for (int m = m0; m < m1; m++) {
                        const float4 S = spk[m];                 // LDS.128 broadcast
                        const float dx = px - S.x;
                        const float dy = py - S.y;
                        const float dz = pz - S.z;
                        const float d2 = fmaf(dz, dz, fmaf(dy, dy, dx * dx));
                        if (d2 <= bd[KNN - 1]) {
                            float d = d2;
                            int kk = __float_as_int(S.w) | m;
#pragma unroll
                            for (int k = 0; k < KNN; k++) {
                                const bool sw = (d < bd[k]) || ((d == bd[k]) && (kk < bo[k]));
                                if (sw) {
                                    const float td = bd[k]; bd[k] = d;  d = td;
                                    const int   ti = bo[k]; bo[k] = kk; kk = ti;
                                }
                            }
                        }
                    }
                }
            }
        }

        const bool full = (xlo == 0 && xhi == G - 1 && ylo == 0 && yhi == G - 1 &&
                           zlo == 0 && zhi == G - 1);
        if (!ldone) {
            // Per-lane ring bound against the visited box; clamped faces need no bound.
            float bnd = 3.0e38f;
            if (xlo > 0)     bnd = fminf(bnd, px - (mnx + (float)xlo * hx));
            if (xhi < G - 1) bnd = fminf(bnd, (mnx + (float)(xhi + 1) * hx) - px);
            if (ylo > 0)     bnd = fminf(bnd, py - (mny + (float)ylo * hy));
            if (yhi < G - 1) bnd = fminf(bnd, (mny + (float)(yhi + 1) * hy) - py);
            if (zlo > 0)     bnd = fminf(bnd, pz - (mnz + (float)zlo * hz));
            if (zhi < G - 1) bnd = fminf(bnd, (mnz + (float)(zhi + 1) * hz) - pz);
            ldone = full || (bd[KNN - 1] < 3.0e38f && bnd > 0.0f &&
                             bnd * bnd >= bd[KNN - 1] * 1.0002f);
        }
        if (__all_sync(FULL, ldone) || full) break;
        pxl = xlo; pxh = xhi; pyl = ylo; pyh = yhi; pzl = zlo; pzh = zhi;
    }

    // Voronoi-edge epilogue on the 11 selected sites (slots 1..10 order irrelevant: min)
    const int p0 = bo[0] & 4095;
    const float4 C = spk[p0];
    const float tx = px - C.x, ty = py - C.y, tz = pz - C.z;
    float best = 3.4e38f;
#pragma unroll
    for (int j = 1; j < KNN; j++) {
        const int pj = bo[j] & 4095;
        const float4 E = spk[pj];
        const float ex = E.x - C.x, ey = E.y - C.y, ez = E.z - C.z;
        const float el2 = fmaf(ez, ez, fmaf(ey, ey, ex * ex));
        const float dp  = fmaf(tz, ez, fmaf(ty, ey, tx * ex));
        const float tt  = fmaf(-0.5f, el2, dp) * rsqrtf(el2);  // (dp - el2/2)/sqrt(el2)
        best = fminf(best, tt * tt);
    }
    if (valid) out[(size_t)b * NPTS + orig] = best;
}

// ---------------- launch ----------------
extern "C" void kernel_launch(void* const* d_in, const int* in_sizes, int n_in,
                              void* d_out, int out_size)
{
    const float* points  = (const float*)d_in[0];
    const float* spoints = (const float*)d_in[1];
    float* out = (float*)d_out;

    cudaFuncSetAttribute(k_setup_sites, cudaFuncAttributeMaxDynamicSharedMemorySize, SM_SETUP);
    cudaFuncSetAttribute(k_main,        cudaFuncAttributeMaxDynamicSharedMemorySize, SM_MAIN);

    k_setup_sites<<<NB, 256, SM_SETUP>>>(spoints);
    dim3 gp((NPTS + 255) / 256, NB);
    k_count_pts<<<gp, 256>>>(points);
    k_init_cursors<<<NB, 256>>>();
    k_scatter_pts<<<gp, 256>>>(points);
    k_main<<<dim3(GRID_MAIN, NB), TMAIN, SM_MAIN>>>(out);
}